// round 11
// baseline (speedup 1.0000x reference)
#include <cuda_runtime.h>
#include <cuda_bf16.h>
#include <math.h>
#include <stdint.h>

#define BB 16
#define LL 4096
#define PD 512
#define HH 256
#define NB 2048            // rank buckets
#define NCH 8              // fp32 K chunks of 64

// ---------------------------------------------------------------------------
// scratch (static device memory — no allocations allowed)
// ---------------------------------------------------------------------------
__device__ int   g_keptlist[BB * LL];
__device__ int   g_lenkeep[BB];
__device__ float g_fsemb[BB * HH];
// per chunk c: [Bhi 256x64 | Blo 256x64] flat = 32768 bf16; 8 chunks = 512 KB
__device__ __align__(1024) __nv_bfloat16 g_Bs[8 * 32768];

// ---------------------------------------------------------------------------
// PTX helpers (plain sm_80/90 PTX — no 'a'-gated instructions)
// ---------------------------------------------------------------------------
__device__ __forceinline__ uint32_t smem_u32(const void* p) {
    uint32_t a;
    asm("{ .reg .u64 t; cvta.to.shared.u64 t, %1; cvt.u32.u64 %0, t; }" : "=r"(a) : "l"(p));
    return a;
}
__device__ __forceinline__ void cp16(uint32_t s, const void* g) {
    asm volatile("cp.async.cg.shared.global [%0], [%1], 16;" :: "r"(s), "l"(g));
}
#define CP_COMMIT() asm volatile("cp.async.commit_group;" ::: "memory")

__device__ __forceinline__ void ldsm4(uint32_t* r, uint32_t a) {
    asm volatile("ldmatrix.sync.aligned.m8n8.x4.shared.b16 {%0,%1,%2,%3}, [%4];"
                 : "=r"(r[0]), "=r"(r[1]), "=r"(r[2]), "=r"(r[3]) : "r"(a));
}
__device__ __forceinline__ void mma16816(float* d, const uint32_t* a,
                                         uint32_t b0, uint32_t b1) {
    asm volatile(
        "mma.sync.aligned.m16n8k16.row.col.f32.bf16.bf16.f32 "
        "{%0,%1,%2,%3}, {%4,%5,%6,%7}, {%8,%9}, {%0,%1,%2,%3};"
        : "+f"(d[0]), "+f"(d[1]), "+f"(d[2]), "+f"(d[3])
        : "r"(a[0]), "r"(a[1]), "r"(a[2]), "r"(a[3]), "r"(b0), "r"(b1));
}

// ---------------------------------------------------------------------------
// block-wide exclusive scan over one int per thread (1024 threads)
// ---------------------------------------------------------------------------
__device__ __forceinline__ int block_exscan(int v, int* wsum) {
    int lane = threadIdx.x & 31, wid = threadIdx.x >> 5;
    int inc = v;
#pragma unroll
    for (int d = 1; d < 32; d <<= 1) {
        int u = __shfl_up_sync(0xffffffffu, inc, d);
        if (lane >= d) inc += u;
    }
    if (lane == 31) wsum[wid] = inc;
    __syncthreads();
    if (wid == 0) {
        int s = wsum[lane];
#pragma unroll
        for (int d = 1; d < 32; d <<= 1) {
            int u = __shfl_up_sync(0xffffffffu, s, d);
            if (lane >= d) s += u;
        }
        wsum[lane] = s;
    }
    __syncthreads();
    return ((wid > 0) ? wsum[wid - 1] : 0) + (inc - v);
}

// ---------------------------------------------------------------------------
// k_front: role-dispatched front kernel, grid 48 x 1024 threads.
//   blocks  0..15 : prep (sort/rank/scan) for batch b = blockIdx.x
//   blocks 16..31 : timestep MLP (both layers) for b = blockIdx.x - 16
//   blocks 32..47 : W fp32 -> [Bhi|Blo] bf16 conversion (1/16 slice each)
// ---------------------------------------------------------------------------
__global__ void __launch_bounds__(1024, 1)
k_front(const int* __restrict__ sids, const int* __restrict__ eff_lens,
        const float* __restrict__ noise, float* __restrict__ out,
        const float* __restrict__ fs,
        const float* __restrict__ w1, const float* __restrict__ b1,
        const float* __restrict__ w2, const float* __restrict__ b2,
        const float* __restrict__ W) {
    __shared__ unsigned long long s_keys[LL];   // 32 KB (prep) / reused by fs
    __shared__ int s_hist[NB + 1];
    __shared__ int s_wsum[32];
    __shared__ int s_ns;

    int t = threadIdx.x;
    int lane = t & 31, wid = t >> 5;

    // ======================= role: convW (blocks 32..47) ====================
    if (blockIdx.x >= 32) {
        int gid = (blockIdx.x - 32) * 1024 + t;   // 16384 items
        int row = gid >> 6;          // 0..255
        int g   = gid & 63;          // col group of 8 f32
        int c   = g >> 3;            // chunk
        int cc  = (g & 7) * 8;       // col within chunk
        float4 v0 = *(const float4*)&W[(size_t)row * PD + g * 8];
        float4 v1 = *(const float4*)&W[(size_t)row * PD + g * 8 + 4];
        float a[8] = {v0.x, v0.y, v0.z, v0.w, v1.x, v1.y, v1.z, v1.w};
        __align__(16) __nv_bfloat16 oh[8], ol[8];
#pragma unroll
        for (int i = 0; i < 8; i++) {
            __nv_bfloat16 h = __float2bfloat16_rn(a[i]);
            oh[i] = h;
            ol[i] = __float2bfloat16_rn(a[i] - __bfloat162float(h));
        }
        *(uint4*)&g_Bs[c * 32768 + row * 64 + cc]         = *(const uint4*)oh;
        *(uint4*)&g_Bs[c * 32768 + 16384 + row * 64 + cc] = *(const uint4*)ol;
        return;
    }

    // ======================= role: fs MLP (blocks 16..31) ===================
    if (blockIdx.x >= 16) {
        int b = blockIdx.x - 16;
        float* tf = (float*)s_keys;        // 256 floats
        float* h1 = tf + 256;              // 256 floats
        if (t < 128) {
            float fr = expf(-9.2103403719761836f * (float)t * (1.0f / 128.0f));
            float arg = fs[b] * fr;
            tf[t] = cosf(arg);
            tf[t + 128] = sinf(arg);
        }
        __syncthreads();
        {   // layer 1: 32 warps x 8 outputs each
            float tv[8];
#pragma unroll
            for (int i = 0; i < 8; i++) tv[i] = tf[lane * 8 + i];
#pragma unroll
            for (int j = 0; j < 8; j++) {
                int h = wid * 8 + j;
                float4 a0 = *(const float4*)&w1[h * 256 + lane * 8];
                float4 a1 = *(const float4*)&w1[h * 256 + lane * 8 + 4];
                float s = tv[0]*a0.x + tv[1]*a0.y + tv[2]*a0.z + tv[3]*a0.w
                        + tv[4]*a1.x + tv[5]*a1.y + tv[6]*a1.z + tv[7]*a1.w;
#pragma unroll
                for (int d = 16; d > 0; d >>= 1) s += __shfl_down_sync(0xffffffffu, s, d);
                if (lane == 0) { s += b1[h]; h1[h] = s / (1.0f + expf(-s)); }
            }
        }
        __syncthreads();
        {   // layer 2
            float hv[8];
#pragma unroll
            for (int i = 0; i < 8; i++) hv[i] = h1[lane * 8 + i];
#pragma unroll
            for (int j = 0; j < 8; j++) {
                int h = wid * 8 + j;
                float4 a0 = *(const float4*)&w2[h * 256 + lane * 8];
                float4 a1 = *(const float4*)&w2[h * 256 + lane * 8 + 4];
                float s = hv[0]*a0.x + hv[1]*a0.y + hv[2]*a0.z + hv[3]*a0.w
                        + hv[4]*a1.x + hv[5]*a1.y + hv[6]*a1.z + hv[7]*a1.w;
#pragma unroll
                for (int d = 16; d > 0; d >>= 1) s += __shfl_down_sync(0xffffffffu, s, d);
                if (lane == 0) g_fsemb[b * 256 + h] = s + b2[h];
            }
        }
        return;
    }

    // ======================= role: prep (blocks 0..15) ======================
    int b = blockIdx.x;
    int eff = eff_lens[b];
    int base = t * 4;

    s_hist[t] = 0;
    if (t < NB + 1 - 1024) s_hist[1024 + t] = 0;
    if (t == 0) { s_hist[NB] = 0; s_ns = 0; }

    int4  sd4 = *(const int4*)  &sids [b * LL + base];
    float4 nz4 = *(const float4*)&noise[b * LL + base];
    int sm1 = (base >= 1) ? sids[b * LL + base - 1] : -1;
    int sm2 = (base >= 2) ? sids[b * LL + base - 2] : -1;
    __syncthreads();

    int   sd[6] = {sm2, sm1, sd4.x, sd4.y, sd4.z, sd4.w};
    float nz[4] = {nz4.x, nz4.y, nz4.z, nz4.w};

    unsigned long long key[4];
    int bid[4], slot[4];
    int nseg = 0;
#pragma unroll
    for (int i = 0; i < 4; i++) {
        int l = base + i;
        bool valid = l < eff;
        bool seg = valid && (sd[i + 2] != sd[i + 1]);
        bool fst = valid && (l >= 1) && (sd[i + 1] != sd[i]);
        nseg += seg ? 1 : 0;
        float v = (seg || fst) ? 0.0f : nz[i];
        unsigned int bits = __float_as_uint(v);
        key[i] = ((unsigned long long)bits << 12) | (unsigned)l;
        bid[i] = min(NB - 1, (int)(v * (float)NB));
        if (valid) slot[i] = atomicAdd(&s_hist[bid[i]], 1);
    }
    {
        int v = nseg;
#pragma unroll
        for (int d = 16; d > 0; d >>= 1) v += __shfl_down_sync(0xffffffffu, v, d);
        if (lane == 0 && v) atomicAdd(&s_ns, v);
    }
    __syncthreads();

    int ns = s_ns;
    int lk = 2 * ns + (int)((float)(eff - 2 * ns) * 0.25f);

    int c0 = s_hist[2 * t], c1 = s_hist[2 * t + 1];
    int ex = block_exscan(c0 + c1, s_wsum);
    s_hist[2 * t] = ex;
    s_hist[2 * t + 1] = ex + c0;
    if (t == 1023) s_hist[NB] = ex + c0 + c1;
    __syncthreads();

#pragma unroll
    for (int i = 0; i < 4; i++) {
        int l = base + i;
        if (l < eff) s_keys[s_hist[bid[i]] + slot[i]] = key[i];
    }
    __syncthreads();

    int r[4];
    bool kept[4];
    int cnt = 0;
#pragma unroll
    for (int i = 0; i < 4; i++) {
        int l = base + i;
        if (l < eff) {
            int lo = s_hist[bid[i]], hi = s_hist[bid[i] + 1];
            int c = 0;
            for (int m = lo; m < hi; m++) c += (s_keys[m] < key[i]) ? 1 : 0;
            r[i] = lo + c;
        } else {
            r[i] = l;
        }
        kept[i] = (l < eff) && (r[i] < lk);
        cnt += kept[i] ? 1 : 0;
    }
    __syncthreads();

    int p = block_exscan(cnt, s_wsum);

    const size_t O1 = (size_t)BB * LL * HH;
    const size_t O2 = O1 + (size_t)BB * LL;
    const size_t O3 = O2 + (size_t)BB * LL;
    float* mae = out + O1 + (size_t)b * LL;
    float* rst = out + O2 + (size_t)b * LL;
    float* unm = out + O3 + (size_t)b * LL;

#pragma unroll
    for (int i = 0; i < 4; i++) {
        int l = base + i;
        mae[l] = (l < eff && !kept[i]) ? 1.0f : 0.0f;
        rst[l] = (float)(kept[i] ? p : r[i]);
        if (kept[i]) {
            g_keptlist[b * LL + p] = l;
            unm[p] = (float)sd[i + 2];
            p++;
        }
        if (l >= lk) unm[l] = -1.0f;
    }
    if (t == 0) g_lenkeep[b] = lk;
}

// ---------------------------------------------------------------------------
// k_gemm: fused convert + mma.sync bf16 3-term GEMM + tail zeroing.
// Block (256 thr, 8 warps) = (M-tile 128, N-half 128, batch); 2 CTAs/SM.
// 8 fp32 K-chunks of 64 cols.  Per chunk: inline LDG gather + convert of A
// into single-buffered A'hi/lo smem; B' via double-buffered cp.async.
// SMEM from 128-aligned base AB:
//   0: sBF[128]f  512: sKL[128]i
//   2048:  A' (hi 16K @+0, lo 16K @+16384) = 32 KB (single buffer)
//   34816: B' buf x2 (each: hi 16K @+0, lo 16K @+16384) = 64 KB
// Total 100352 B -> 2 CTAs/SM (227 KB cap).
// ---------------------------------------------------------------------------
#define SM_AP 2048
#define SM_BP 34816
#define SMEMSZ 100352

__global__ void __launch_bounds__(256, 2)
k_gemm(const float* __restrict__ patches,
       const float* __restrict__ bias, const float* __restrict__ pos,
       float* __restrict__ out_seq) {
    extern __shared__ char dsm[];
    int b  = blockIdx.z;
    int n0 = blockIdx.y * 128;
    int p0 = blockIdx.x * 128;
    int lk = g_lenkeep[b];
    int t = threadIdx.x;

    // ---- pure-zero blocks: whole tile is tail (block-uniform branch) ----
    if (p0 >= lk) {
        float4 z = make_float4(0.f, 0.f, 0.f, 0.f);
#pragma unroll
        for (int i = 0; i < 16; i++) {
            int idx = t + i * 256;       // 4096 float4s: 128 rows x 32 f4
            int row = idx >> 5, c4 = idx & 31;
            *((float4*)&out_seq[((size_t)b * LL + p0 + row) * HH + n0] + c4) = z;
        }
        return;
    }

    uint32_t AB = (smem_u32(dsm) + 127u) & ~127u;
    char* ABp = dsm + (AB - smem_u32(dsm));
    float* sBF = (float*)(ABp);
    int*   sKL = (int*)(ABp + 512);

    int lane = t & 31, wid = t >> 5;
    int wm = wid & 3, wn = wid >> 2;       // 4 M-groups x 2 N-groups

    if (t < 128) {
        sBF[t] = bias[n0 + t] + g_fsemb[b * HH + n0 + t];
        int p = p0 + t;
        sKL[t] = (p < lk) ? g_keptlist[b * LL + p] : 0;
    }
    __syncthreads();   // sKL needed for LDG addresses

    // ---- A gather/convert mapping: row = t&127, col-half hs = t>>7 ----
    int cvr = t & 127;
    int hs  = t >> 7;
    const float* aPtr = &patches[((size_t)b * LL + sKL[cvr]) * PD + hs * 32];
    uint32_t aRowOff = (uint32_t)(SM_AP + cvr * 128);
    uint32_t aSegSwz[4];
#pragma unroll
    for (int j = 0; j < 4; j++)
        aSegSwz[j] = (uint32_t)((((hs * 4 + j) ^ (cvr & 7)) * 16));

    // ---- ldmatrix address components ----
    uint32_t aRB[2], aXP[2];
#pragma unroll
    for (int mt = 0; mt < 2; mt++) {
        int rowA = wm * 32 + mt * 16 + (lane & 15);
        aRB[mt] = AB + SM_AP + (uint32_t)(rowA * 128);
        aXP[mt] = (uint32_t)((rowA & 7) << 4);
    }
    uint32_t aSG = (uint32_t)((lane >> 4) * 16);
    uint32_t bRB[4], bXP[4];
#pragma unroll
    for (int g = 0; g < 4; g++) {
        int rowB = wn * 64 + g * 16 + ((lane >> 4) << 3) + (lane & 7);  // 0..127
        bRB[g] = AB + SM_BP + (uint32_t)(rowB * 128);
        bXP[g] = (uint32_t)((rowB & 7) << 4);
    }
    uint32_t bSG = (uint32_t)(((lane >> 3) & 1) * 16);

    float acc[2][8][4];
#pragma unroll
    for (int mt = 0; mt < 2; mt++)
#pragma unroll
        for (int nt = 0; nt < 8; nt++)
#pragma unroll
            for (int i = 0; i < 4; i++) acc[mt][nt][i] = 0.f;

    // B' copy: 2048 segs of 16B (32 KB: hi 128x64 + lo 128x64 for this N-half)
    auto cp_B = [&](int c) {
        uint32_t bb = AB + SM_BP + (uint32_t)(c & 1) * 32768u;
        const __nv_bfloat16* Bg = &g_Bs[c * 32768];
#pragma unroll
        for (int i = 0; i < 8; i++) {
            int sid = t + i * 256;
            int r = sid >> 3, s = sid & 7;
            int rr = r & 127;
            uint32_t half = (r >= 128) ? 16384u : 0u;
            cp16(bb + half + (uint32_t)(rr * 128 + ((s ^ (rr & 7)) * 16)),
                 Bg + (r >= 128 ? 16384 : 0) + (n0 + rr) * 64 + s * 8);
        }
        CP_COMMIT();
    };

    // inline LDG + convert of A chunk c into A' (single buffer)
    auto conv_A = [&](int c) {
        float4 av[8];
#pragma unroll
        for (int i = 0; i < 8; i++)
            av[i] = __ldg((const float4*)(aPtr + c * 64 + i * 4));
#pragma unroll
        for (int j = 0; j < 4; j++) {
            uint32_t hi[4], lo[4];
#pragma unroll
            for (int q = 0; q < 2; q++) {
                float4 v = av[j * 2 + q];
                __nv_bfloat162 h01 = __float22bfloat162_rn(make_float2(v.x, v.y));
                __nv_bfloat162 h23 = __float22bfloat162_rn(make_float2(v.z, v.w));
                float2 hf01 = __bfloat1622float2(h01);
                float2 hf23 = __bfloat1622float2(h23);
                __nv_bfloat162 l01 = __float22bfloat162_rn(make_float2(v.x - hf01.x, v.y - hf01.y));
                __nv_bfloat162 l23 = __float22bfloat162_rn(make_float2(v.z - hf23.x, v.w - hf23.y));
                hi[q * 2]     = *(uint32_t*)&h01;
                hi[q * 2 + 1] = *(uint32_t*)&h23;
                lo[q * 2]     = *(uint32_t*)&l01;
                lo[q * 2 + 1] = *(uint32_t*)&l23;
            }
            *(uint4*)(ABp + aRowOff + aSegSwz[j])         = make_uint4(hi[0], hi[1], hi[2], hi[3]);
            *(uint4*)(ABp + aRowOff + 16384 + aSegSwz[j]) = make_uint4(lo[0], lo[1], lo[2], lo[3]);
        }
    };

    cp_B(0);

    for (int c = 0; c < NCH; c++) {
        uint32_t bb = (uint32_t)(c & 1) * 32768u;
        if (c + 1 < NCH) {
            cp_B(c + 1);
            asm volatile("cp.async.wait_group 1;" ::: "memory");   // B(c) done
        } else {
            asm volatile("cp.async.wait_group 0;" ::: "memory");
        }
        conv_A(c);               // A' single buffer (prev readers done: bottom sync)
        __syncthreads();         // A' + B'(c) visible

        // ---- MMA: 4 k16 stages x 3 terms ----
#pragma unroll
        for (int s = 0; s < 4; s++) {
            uint32_t ah[2][4], al[2][4], bf[4][4];
            uint32_t so = (uint32_t)(s * 32);
#pragma unroll
            for (int mt = 0; mt < 2; mt++) {
                uint32_t off = (so + aSG) ^ aXP[mt];
                ldsm4(ah[mt], aRB[mt] + off);
                ldsm4(al[mt], aRB[mt] + 16384u + off);
            }
#pragma unroll
            for (int g = 0; g < 4; g++)
                ldsm4(bf[g], bRB[g] + bb + ((so + bSG) ^ bXP[g]));
#pragma unroll
            for (int mt = 0; mt < 2; mt++)
#pragma unroll
                for (int nt = 0; nt < 8; nt++)
                    mma16816(acc[mt][nt], ah[mt],
                             bf[nt >> 1][(nt & 1) * 2], bf[nt >> 1][(nt & 1) * 2 + 1]);
#pragma unroll
            for (int mt = 0; mt < 2; mt++)
#pragma unroll
                for (int nt = 0; nt < 8; nt++)
                    mma16816(acc[mt][nt], al[mt],
                             bf[nt >> 1][(nt & 1) * 2], bf[nt >> 1][(nt & 1) * 2 + 1]);
#pragma unroll
            for (int g = 0; g < 4; g++)  // Blo region = +16384 within buf
                ldsm4(bf[g], bRB[g] + bb + 16384u + ((so + bSG) ^ bXP[g]));
#pragma unroll
            for (int mt = 0; mt < 2; mt++)
#pragma unroll
                for (int nt = 0; nt < 8; nt++)
                    mma16816(acc[mt][nt], ah[mt],
                             bf[nt >> 1][(nt & 1) * 2], bf[nt >> 1][(nt & 1) * 2 + 1]);
        }
        __syncthreads();   // A' readers done (next conv overwrites); B buf free
    }

    // ---- epilogue: acc + bias + fsemb + pos -> out; tail rows -> 0 ----
#pragma unroll
    for (int mt = 0; mt < 2; mt++) {
        int rbase = wm * 32 + mt * 16 + (lane >> 2);
#pragma unroll
        for (int h = 0; h < 2; h++) {
            int rr = rbase + h * 8;
            int p = p0 + rr;
            int kl = sKL[rr];
            bool ok = p < lk;
            float* orow = &out_seq[(((size_t)b * LL) + p) * HH + n0];
            const float* prow = &pos[(size_t)kl * HH + n0];
#pragma unroll
            for (int nt = 0; nt < 8; nt++) {
                int col = wn * 64 + nt * 8 + (lane & 3) * 2;
                float2 v;
                if (ok) {
                    v.x = acc[mt][nt][h * 2 + 0] + sBF[col]     + prow[col];
                    v.y = acc[mt][nt][h * 2 + 1] + sBF[col + 1] + prow[col + 1];
                } else {
                    v.x = 0.f; v.y = 0.f;
                }
                *(float2*)&orow[col] = v;
            }
        }
    }
}

// ---------------------------------------------------------------------------
extern "C" void kernel_launch(void* const* d_in, const int* in_sizes, int n_in,
                              void* d_out, int out_size) {
    const float* patches = (const float*)d_in[0];
    const int*   sids    = (const int*)  d_in[1];
    const int*   eff     = (const int*)  d_in[2];
    const float* noise   = (const float*)d_in[3];
    const float* fs      = (const float*)d_in[4];
    const float* W       = (const float*)d_in[5];
    const float* bias    = (const float*)d_in[6];
    const float* pos     = (const float*)d_in[7];
    const float* w1      = (const float*)d_in[8];
    const float* b1      = (const float*)d_in[9];
    const float* w2      = (const float*)d_in[10];
    const float* b2      = (const float*)d_in[11];
    float* out = (float*)d_out;

    cudaFuncSetAttribute(k_gemm, cudaFuncAttributeMaxDynamicSharedMemorySize, SMEMSZ);

    k_front<<<48, 1024>>>(sids, eff, noise, out, fs, w1, b1, w2, b2, W);
    k_gemm<<<dim3(32, 2, BB), 256, SMEMSZ>>>(patches, bias, pos, out);

    (void)in_sizes; (void)n_in; (void)out_size;
}

// round 13
// speedup vs baseline: 1.2598x; 1.2598x over previous
#include <cuda_runtime.h>
#include <cuda_bf16.h>
#include <math.h>
#include <stdint.h>

#define BB 16
#define LL 4096
#define PD 512
#define HH 256
#define NB 2048            // rank buckets
#define NCH 8              // K chunks of 64 fp32 cols

// ---------------------------------------------------------------------------
// scratch (static device memory — no allocations allowed)
// ---------------------------------------------------------------------------
__device__ int   g_keptlist[BB * LL];
__device__ int   g_lenkeep[BB];
__device__ float g_fsemb[BB * HH];
// W as tf32 (u32), per chunk c: 2 subtiles [256 rows x 32 k] = 16384 u32; 512 KB
__device__ __align__(1024) uint32_t g_Bs[8 * 16384];

// ---------------------------------------------------------------------------
// PTX helpers (plain sm_80/90 PTX — no 'a'-gated instructions)
// ---------------------------------------------------------------------------
__device__ __forceinline__ uint32_t smem_u32(const void* p) {
    uint32_t a;
    asm("{ .reg .u64 t; cvta.to.shared.u64 t, %1; cvt.u32.u64 %0, t; }" : "=r"(a) : "l"(p));
    return a;
}
__device__ __forceinline__ void cp16(uint32_t s, const void* g) {
    asm volatile("cp.async.cg.shared.global [%0], [%1], 16;" :: "r"(s), "l"(g));
}
#define CP_COMMIT() asm volatile("cp.async.commit_group;" ::: "memory")

__device__ __forceinline__ void ldsm4(uint32_t* r, uint32_t a) {
    asm volatile("ldmatrix.sync.aligned.m8n8.x4.shared.b16 {%0,%1,%2,%3}, [%4];"
                 : "=r"(r[0]), "=r"(r[1]), "=r"(r[2]), "=r"(r[3]) : "r"(a));
}
__device__ __forceinline__ uint32_t f2tf32(float x) {
    uint32_t u;
    asm("cvt.rna.tf32.f32 %0, %1;" : "=r"(u) : "f"(x));
    return u;
}
__device__ __forceinline__ void mma_tf32(float* d, const uint32_t* a,
                                         uint32_t b0, uint32_t b1) {
    asm volatile(
        "mma.sync.aligned.m16n8k8.row.col.f32.tf32.tf32.f32 "
        "{%0,%1,%2,%3}, {%4,%5,%6,%7}, {%8,%9}, {%0,%1,%2,%3};"
        : "+f"(d[0]), "+f"(d[1]), "+f"(d[2]), "+f"(d[3])
        : "r"(a[0]), "r"(a[1]), "r"(a[2]), "r"(a[3]), "r"(b0), "r"(b1));
}

// ---------------------------------------------------------------------------
// block-wide exclusive scan over one int per thread (1024 threads)
// ---------------------------------------------------------------------------
__device__ __forceinline__ int block_exscan(int v, int* wsum) {
    int lane = threadIdx.x & 31, wid = threadIdx.x >> 5;
    int inc = v;
#pragma unroll
    for (int d = 1; d < 32; d <<= 1) {
        int u = __shfl_up_sync(0xffffffffu, inc, d);
        if (lane >= d) inc += u;
    }
    if (lane == 31) wsum[wid] = inc;
    __syncthreads();
    if (wid == 0) {
        int s = wsum[lane];
#pragma unroll
        for (int d = 1; d < 32; d <<= 1) {
            int u = __shfl_up_sync(0xffffffffu, s, d);
            if (lane >= d) s += u;
        }
        wsum[lane] = s;
    }
    __syncthreads();
    return ((wid > 0) ? wsum[wid - 1] : 0) + (inc - v);
}

// ---------------------------------------------------------------------------
// k_front: role-dispatched front kernel, grid 48 x 1024 threads.
//   blocks  0..15 : prep (sort/rank/scan) for batch b = blockIdx.x
//   blocks 16..31 : timestep MLP (both layers) for b = blockIdx.x - 16
//   blocks 32..47 : W fp32 -> tf32 conversion (1/16 slice each)
// ---------------------------------------------------------------------------
__global__ void __launch_bounds__(1024, 1)
k_front(const int* __restrict__ sids, const int* __restrict__ eff_lens,
        const float* __restrict__ noise, float* __restrict__ out,
        const float* __restrict__ fs,
        const float* __restrict__ w1, const float* __restrict__ b1,
        const float* __restrict__ w2, const float* __restrict__ b2,
        const float* __restrict__ W) {
    __shared__ unsigned long long s_keys[LL];   // 32 KB (prep) / reused by fs
    __shared__ int s_hist[NB + 1];
    __shared__ int s_wsum[32];
    __shared__ int s_ns;

    int t = threadIdx.x;
    int lane = t & 31, wid = t >> 5;

    // ======================= role: convW (blocks 32..47) ====================
    if (blockIdx.x >= 32) {
        int gid = (blockIdx.x - 32) * 1024 + t;   // 16384 items
        int row = gid >> 6;          // 0..255
        int g   = gid & 63;          // col group of 8 f32 (k = g*8..g*8+7)
        int c   = g >> 3;            // chunk (k>>6)
        int h   = (g >> 2) & 1;      // subtile (k>>5)&1
        int kk  = (g & 3) * 8;       // k within subtile (0..31 step 8)
        float4 v0 = *(const float4*)&W[(size_t)row * PD + g * 8];
        float4 v1 = *(const float4*)&W[(size_t)row * PD + g * 8 + 4];
        float a[8] = {v0.x, v0.y, v0.z, v0.w, v1.x, v1.y, v1.z, v1.w};
        uint32_t o[8];
#pragma unroll
        for (int i = 0; i < 8; i++) o[i] = f2tf32(a[i]);
        uint32_t* dst = &g_Bs[c * 16384 + h * 8192 + row * 32 + kk];
        *(uint4*)(dst)     = make_uint4(o[0], o[1], o[2], o[3]);
        *(uint4*)(dst + 4) = make_uint4(o[4], o[5], o[6], o[7]);
        return;
    }

    // ======================= role: fs MLP (blocks 16..31) ===================
    if (blockIdx.x >= 16) {
        int b = blockIdx.x - 16;
        float* tf = (float*)s_keys;        // 256 floats
        float* h1 = tf + 256;              // 256 floats
        if (t < 128) {
            float fr = expf(-9.2103403719761836f * (float)t * (1.0f / 128.0f));
            float arg = fs[b] * fr;
            tf[t] = cosf(arg);
            tf[t + 128] = sinf(arg);
        }
        __syncthreads();
        {   // layer 1: 32 warps x 8 outputs each
            float tv[8];
#pragma unroll
            for (int i = 0; i < 8; i++) tv[i] = tf[lane * 8 + i];
#pragma unroll
            for (int j = 0; j < 8; j++) {
                int h = wid * 8 + j;
                float4 a0 = *(const float4*)&w1[h * 256 + lane * 8];
                float4 a1 = *(const float4*)&w1[h * 256 + lane * 8 + 4];
                float s = tv[0]*a0.x + tv[1]*a0.y + tv[2]*a0.z + tv[3]*a0.w
                        + tv[4]*a1.x + tv[5]*a1.y + tv[6]*a1.z + tv[7]*a1.w;
#pragma unroll
                for (int d = 16; d > 0; d >>= 1) s += __shfl_down_sync(0xffffffffu, s, d);
                if (lane == 0) { s += b1[h]; h1[h] = s / (1.0f + expf(-s)); }
            }
        }
        __syncthreads();
        {   // layer 2
            float hv[8];
#pragma unroll
            for (int i = 0; i < 8; i++) hv[i] = h1[lane * 8 + i];
#pragma unroll
            for (int j = 0; j < 8; j++) {
                int h = wid * 8 + j;
                float4 a0 = *(const float4*)&w2[h * 256 + lane * 8];
                float4 a1 = *(const float4*)&w2[h * 256 + lane * 8 + 4];
                float s = hv[0]*a0.x + hv[1]*a0.y + hv[2]*a0.z + hv[3]*a0.w
                        + hv[4]*a1.x + hv[5]*a1.y + hv[6]*a1.z + hv[7]*a1.w;
#pragma unroll
                for (int d = 16; d > 0; d >>= 1) s += __shfl_down_sync(0xffffffffu, s, d);
                if (lane == 0) g_fsemb[b * 256 + h] = s + b2[h];
            }
        }
        return;
    }

    // ======================= role: prep (blocks 0..15) ======================
    int b = blockIdx.x;
    int eff = eff_lens[b];
    int base = t * 4;

    s_hist[t] = 0;
    if (t < NB + 1 - 1024) s_hist[1024 + t] = 0;
    if (t == 0) { s_hist[NB] = 0; s_ns = 0; }

    int4  sd4 = *(const int4*)  &sids [b * LL + base];
    float4 nz4 = *(const float4*)&noise[b * LL + base];
    int sm1 = (base >= 1) ? sids[b * LL + base - 1] : -1;
    int sm2 = (base >= 2) ? sids[b * LL + base - 2] : -1;
    __syncthreads();

    int   sd[6] = {sm2, sm1, sd4.x, sd4.y, sd4.z, sd4.w};
    float nz[4] = {nz4.x, nz4.y, nz4.z, nz4.w};

    unsigned long long key[4];
    int bid[4], slot[4];
    int nseg = 0;
#pragma unroll
    for (int i = 0; i < 4; i++) {
        int l = base + i;
        bool valid = l < eff;
        bool seg = valid && (sd[i + 2] != sd[i + 1]);
        bool fst = valid && (l >= 1) && (sd[i + 1] != sd[i]);
        nseg += seg ? 1 : 0;
        float v = (seg || fst) ? 0.0f : nz[i];
        unsigned int bits = __float_as_uint(v);
        key[i] = ((unsigned long long)bits << 12) | (unsigned)l;
        bid[i] = min(NB - 1, (int)(v * (float)NB));
        if (valid) slot[i] = atomicAdd(&s_hist[bid[i]], 1);
    }
    {
        int v = nseg;
#pragma unroll
        for (int d = 16; d > 0; d >>= 1) v += __shfl_down_sync(0xffffffffu, v, d);
        if (lane == 0 && v) atomicAdd(&s_ns, v);
    }
    __syncthreads();

    int ns = s_ns;
    int lk = 2 * ns + (int)((float)(eff - 2 * ns) * 0.25f);

    int c0 = s_hist[2 * t], c1 = s_hist[2 * t + 1];
    int ex = block_exscan(c0 + c1, s_wsum);
    s_hist[2 * t] = ex;
    s_hist[2 * t + 1] = ex + c0;
    if (t == 1023) s_hist[NB] = ex + c0 + c1;
    __syncthreads();

#pragma unroll
    for (int i = 0; i < 4; i++) {
        int l = base + i;
        if (l < eff) s_keys[s_hist[bid[i]] + slot[i]] = key[i];
    }
    __syncthreads();

    int r[4];
    bool kept[4];
    int cnt = 0;
#pragma unroll
    for (int i = 0; i < 4; i++) {
        int l = base + i;
        if (l < eff) {
            int lo = s_hist[bid[i]], hi = s_hist[bid[i] + 1];
            int c = 0;
            for (int m = lo; m < hi; m++) c += (s_keys[m] < key[i]) ? 1 : 0;
            r[i] = lo + c;
        } else {
            r[i] = l;
        }
        kept[i] = (l < eff) && (r[i] < lk);
        cnt += kept[i] ? 1 : 0;
    }
    __syncthreads();

    int p = block_exscan(cnt, s_wsum);

    const size_t O1 = (size_t)BB * LL * HH;
    const size_t O2 = O1 + (size_t)BB * LL;
    const size_t O3 = O2 + (size_t)BB * LL;
    float* mae = out + O1 + (size_t)b * LL;
    float* rst = out + O2 + (size_t)b * LL;
    float* unm = out + O3 + (size_t)b * LL;

#pragma unroll
    for (int i = 0; i < 4; i++) {
        int l = base + i;
        mae[l] = (l < eff && !kept[i]) ? 1.0f : 0.0f;
        rst[l] = (float)(kept[i] ? p : r[i]);
        if (kept[i]) {
            g_keptlist[b * LL + p] = l;
            unm[p] = (float)sd[i + 2];
            p++;
        }
        if (l >= lk) unm[l] = -1.0f;
    }
    if (t == 0) g_lenkeep[b] = lk;
}

// ---------------------------------------------------------------------------
// k_gemm: tf32 single-term mma.sync GEMM + gather + tail zeroing.
// Block (512 thr, 16 warps) = (batch, M-tile 128).  N=256 whole.
// 8 K-chunks of 64.  A gathered via reg-prefetched LDG -> cvt.rna ->
// double-buffered A-tf32 smem; B via double-buffered cp.async (already tf32).
// A chunk buf: 2 subtiles [128 rows x 32 k x 4B = 128B rows] = 32 KB.
// B chunk buf: 2 subtiles [256 rows x 32 k]                  = 64 KB.
// SMEM from 128-aligned base AB:
//   0: sBF[256]f  1024: sKL[128]i
//   2048:  A bufs x2 = 64 KB     67584: B bufs x2 = 128 KB
// ---------------------------------------------------------------------------
#define SM_AP 2048
#define SM_BP 67584
#define SMEMSZ (198656 + 1024)

__global__ void __launch_bounds__(512, 1)
k_gemm(const float* __restrict__ patches,
       const float* __restrict__ bias, const float* __restrict__ pos,
       float* __restrict__ out_seq) {
    extern __shared__ char dsm[];
    int b  = blockIdx.y;
    int p0 = blockIdx.x * 128;
    int lk = g_lenkeep[b];
    int t = threadIdx.x;

    // ---- pure-zero blocks: whole tile is tail (block-uniform branch) ----
    if (p0 >= lk) {
        float4* dst = (float4*)&out_seq[((size_t)b * LL + p0) * HH];
        float4 z = make_float4(0.f, 0.f, 0.f, 0.f);
#pragma unroll
        for (int i = 0; i < 16; i++) dst[t + i * 512] = z;
        return;
    }

    uint32_t AB = (smem_u32(dsm) + 127u) & ~127u;
    char* ABp = dsm + (AB - smem_u32(dsm));
    float* sBF = (float*)(ABp);
    int*   sKL = (int*)(ABp + 1024);

    int lane = t & 31, wid = t >> 5;
    int wm = wid & 3, wn = wid >> 2;     // 4 M-groups(32) x 4 N-groups(64)

    if (t < 256) sBF[t] = bias[t] + g_fsemb[b * HH + t];
    if (t < 128) {
        int p = p0 + t;
        sKL[t] = (p < lk) ? g_keptlist[b * LL + p] : 0;
    }
    __syncthreads();   // sKL needed for LDG addresses

    // ---- A LDG mapping: row = t>>2, 16 f32 at k = (t&3)*16 ----
    int cvr = t >> 2;
    int cvc = t & 3;
    const float* aPtr = &patches[((size_t)b * LL + sKL[cvr]) * PD + cvc * 16];
    // A store: subtile h = (cvc>>1), segs (cvc&1)*4 + i, swizzle seg^(row&7)
    uint32_t aStBase = (uint32_t)(SM_AP + (cvc >> 1) * 16384 + cvr * 128);
    uint32_t aSegSwz[4];
#pragma unroll
    for (int i = 0; i < 4; i++)
        aSegSwz[i] = (uint32_t)(((((cvc & 1) * 4 + i) ^ (cvr & 7)) * 16));

    // ---- B cp addresses: 4096 segs -> 8 per thread ----
    uint32_t bDst[8];
    int bSrcOff[8];
#pragma unroll
    for (int i = 0; i < 8; i++) {
        int sid = t + i * 512;
        int h = sid >> 11;               // subtile
        int r = (sid >> 3) & 255;        // n row
        int s = sid & 7;                 // 16B seg
        bDst[i] = AB + SM_BP + (uint32_t)(h * 32768 + r * 128 + ((s ^ (r & 7)) * 16));
        bSrcOff[i] = h * 8192 + r * 32 + s * 4;
    }

    // ---- ldmatrix address components ----
    uint32_t aRB[2], aXP[2];
#pragma unroll
    for (int mt = 0; mt < 2; mt++) {
        int rowA = wm * 32 + mt * 16 + (((lane >> 3) & 1) * 8) + (lane & 7);
        aRB[mt] = AB + SM_AP + (uint32_t)(rowA * 128);
        aXP[mt] = (uint32_t)((rowA & 7) << 4);
    }
    uint32_t aSG = (uint32_t)((lane >> 4) * 16);
    uint32_t bRB[4], bXP[4];
#pragma unroll
    for (int g = 0; g < 4; g++) {
        int rowB = wn * 64 + g * 16 + ((lane >> 4) << 3) + (lane & 7);
        bRB[g] = AB + SM_BP + (uint32_t)(rowB * 128);
        bXP[g] = (uint32_t)((rowB & 7) << 4);
    }
    uint32_t bSG = (uint32_t)(((lane >> 3) & 1) * 16);

    float acc[2][8][4];
#pragma unroll
    for (int mt = 0; mt < 2; mt++)
#pragma unroll
        for (int nt = 0; nt < 8; nt++)
#pragma unroll
            for (int i = 0; i < 4; i++) acc[mt][nt][i] = 0.f;

    float4 av[4];

    auto cp_B = [&](int c) {
        uint32_t bb = (uint32_t)(c & 1) * 65536u;
        const uint32_t* Bg = &g_Bs[c * 16384];
#pragma unroll
        for (int i = 0; i < 8; i++) cp16(bDst[i] + bb, Bg + bSrcOff[i]);
        CP_COMMIT();
    };
    auto ldg_A = [&](int c) {
#pragma unroll
        for (int i = 0; i < 4; i++)
            av[i] = __ldg((const float4*)(aPtr + c * 64 + i * 4));
    };
    auto conv_A = [&](int c) {
        uint32_t base = aStBase + (uint32_t)(c & 1) * 32768u;
#pragma unroll
        for (int i = 0; i < 4; i++) {
            float4 v = av[i];
            uint4 o = make_uint4(f2tf32(v.x), f2tf32(v.y), f2tf32(v.z), f2tf32(v.w));
            *(uint4*)(ABp + base + aSegSwz[i]) = o;
        }
    };

    // ---- prologue ----
    cp_B(0);
    ldg_A(0);
    conv_A(0);
    asm volatile("cp.async.wait_group 0;" ::: "memory");
    __syncthreads();

    for (int c = 0; c < NCH; c++) {
        uint32_t ab = (uint32_t)(c & 1) * 32768u;
        uint32_t bb = (uint32_t)(c & 1) * 65536u;
        if (c + 1 < NCH) { cp_B(c + 1); ldg_A(c + 1); }

        // ---- MMA: 8 k8-steps; conv(c+1) inserted after step 0 ----
#pragma unroll
        for (int ks = 0; ks < 8; ks++) {
            uint32_t af[2][4], bf[4][4];
            uint32_t aSub = (uint32_t)((ks >> 2) * 16384) + ab;
            uint32_t bSub = (uint32_t)((ks >> 2) * 32768) + bb;
            uint32_t so = (uint32_t)((ks & 3) * 32);
#pragma unroll
            for (int mt = 0; mt < 2; mt++)
                ldsm4(af[mt], aRB[mt] + aSub + ((so + aSG) ^ aXP[mt]));
#pragma unroll
            for (int g = 0; g < 4; g++)
                ldsm4(bf[g], bRB[g] + bSub + ((so + bSG) ^ bXP[g]));
#pragma unroll
            for (int mt = 0; mt < 2; mt++)
#pragma unroll
                for (int nt = 0; nt < 8; nt++)
                    mma_tf32(acc[mt][nt], af[mt],
                             bf[nt >> 1][(nt & 1) * 2], bf[nt >> 1][(nt & 1) * 2 + 1]);
            if (ks == 0 && c + 1 < NCH) conv_A(c + 1);   // overlaps tensor work
        }
        asm volatile("cp.async.wait_group 0;" ::: "memory");
        __syncthreads();
    }

    // ---- epilogue: acc + bias + fsemb + pos -> out; tail rows -> 0 ----
#pragma unroll
    for (int mt = 0; mt < 2; mt++) {
        int rbase = wm * 32 + mt * 16 + (lane >> 2);
#pragma unroll
        for (int h = 0; h < 2; h++) {
            int rr = rbase + h * 8;
            int p = p0 + rr;
            int kl = sKL[rr];
            bool ok = p < lk;
            float* orow = &out_seq[(((size_t)b * LL) + p) * HH];
            const float* prow = &pos[(size_t)kl * HH];
#pragma unroll
            for (int nt = 0; nt < 8; nt++) {
                int col = wn * 64 + nt * 8 + (lane & 3) * 2;
                float2 v;
                if (ok) {
                    v.x = acc[mt][nt][h * 2 + 0] + sBF[col]     + prow[col];
                    v.y = acc[mt][nt][h * 2 + 1] + sBF[col + 1] + prow[col + 1];
                } else {
                    v.x = 0.f; v.y = 0.f;
                }
                *(float2*)&orow[col] = v;
            }
        }
    }
}

// ---------------------------------------------------------------------------
extern "C" void kernel_launch(void* const* d_in, const int* in_sizes, int n_in,
                              void* d_out, int out_size) {
    const float* patches = (const float*)d_in[0];
    const int*   sids    = (const int*)  d_in[1];
    const int*   eff     = (const int*)  d_in[2];
    const float* noise   = (const float*)d_in[3];
    const float* fs      = (const float*)d_in[4];
    const float* W       = (const float*)d_in[5];
    const float* bias    = (const float*)d_in[6];
    const float* pos     = (const float*)d_in[7];
    const float* w1      = (const float*)d_in[8];
    const float* b1      = (const float*)d_in[9];
    const float* w2      = (const float*)d_in[10];
    const float* b2      = (const float*)d_in[11];
    float* out = (float*)d_out;

    cudaFuncSetAttribute(k_gemm, cudaFuncAttributeMaxDynamicSharedMemorySize, SMEMSZ);

    k_front<<<48, 1024>>>(sids, eff, noise, out, fs, w1, b1, w2, b2, W);
    k_gemm<<<dim3(32, BB), 512, SMEMSZ>>>(patches, bias, pos, out);

    (void)in_sizes; (void)n_in; (void)out_size;
}

// round 15
// speedup vs baseline: 1.3977x; 1.1095x over previous
#include <cuda_runtime.h>
#include <cuda_bf16.h>
#include <math.h>
#include <stdint.h>

#define BB 16
#define LL 4096
#define PD 512
#define HH 256
#define NB 2048            // rank buckets
#define NCH 16             // K chunks of 32 fp32 cols

// ---------------------------------------------------------------------------
// scratch (static device memory — no allocations allowed)
// ---------------------------------------------------------------------------
__device__ int   g_keptlist[BB * LL];
__device__ int   g_lenkeep[BB];
__device__ float g_fsemb[BB * HH];
// W as tf32 (u32): 16 chunks x [256 rows x 32 k] = 8192 u32 each; 512 KB
__device__ __align__(1024) uint32_t g_Bs[16 * 8192];

// ---------------------------------------------------------------------------
// PTX helpers (plain sm_80/90 PTX — no 'a'-gated instructions)
// ---------------------------------------------------------------------------
__device__ __forceinline__ uint32_t smem_u32(const void* p) {
    uint32_t a;
    asm("{ .reg .u64 t; cvta.to.shared.u64 t, %1; cvt.u32.u64 %0, t; }" : "=r"(a) : "l"(p));
    return a;
}
__device__ __forceinline__ void cp16(uint32_t s, const void* g) {
    asm volatile("cp.async.cg.shared.global [%0], [%1], 16;" :: "r"(s), "l"(g));
}
#define CP_COMMIT() asm volatile("cp.async.commit_group;" ::: "memory")

__device__ __forceinline__ void ldsm4(uint32_t* r, uint32_t a) {
    asm volatile("ldmatrix.sync.aligned.m8n8.x4.shared.b16 {%0,%1,%2,%3}, [%4];"
                 : "=r"(r[0]), "=r"(r[1]), "=r"(r[2]), "=r"(r[3]) : "r"(a));
}
__device__ __forceinline__ uint32_t f2tf32(float x) {
    uint32_t u;
    asm("cvt.rna.tf32.f32 %0, %1;" : "=r"(u) : "f"(x));
    return u;
}
__device__ __forceinline__ void mma_tf32(float* d, const uint32_t* a,
                                         uint32_t b0, uint32_t b1) {
    asm volatile(
        "mma.sync.aligned.m16n8k8.row.col.f32.tf32.tf32.f32 "
        "{%0,%1,%2,%3}, {%4,%5,%6,%7}, {%8,%9}, {%0,%1,%2,%3};"
        : "+f"(d[0]), "+f"(d[1]), "+f"(d[2]), "+f"(d[3])
        : "r"(a[0]), "r"(a[1]), "r"(a[2]), "r"(a[3]), "r"(b0), "r"(b1));
}

// ---------------------------------------------------------------------------
// block-wide exclusive scan over one int per thread (1024 threads)
// ---------------------------------------------------------------------------
__device__ __forceinline__ int block_exscan(int v, int* wsum) {
    int lane = threadIdx.x & 31, wid = threadIdx.x >> 5;
    int inc = v;
#pragma unroll
    for (int d = 1; d < 32; d <<= 1) {
        int u = __shfl_up_sync(0xffffffffu, inc, d);
        if (lane >= d) inc += u;
    }
    if (lane == 31) wsum[wid] = inc;
    __syncthreads();
    if (wid == 0) {
        int s = wsum[lane];
#pragma unroll
        for (int d = 1; d < 32; d <<= 1) {
            int u = __shfl_up_sync(0xffffffffu, s, d);
            if (lane >= d) s += u;
        }
        wsum[lane] = s;
    }
    __syncthreads();
    return ((wid > 0) ? wsum[wid - 1] : 0) + (inc - v);
}

// ---------------------------------------------------------------------------
// k_front: role-dispatched front kernel, grid 48 x 1024 threads.
//   blocks  0..15 : prep (sort/rank/scan) for batch b = blockIdx.x
//   blocks 16..31 : timestep MLP (both layers) for b = blockIdx.x - 16
//   blocks 32..47 : W fp32 -> tf32 conversion (1/16 slice each)
// ---------------------------------------------------------------------------
__global__ void __launch_bounds__(1024, 1)
k_front(const int* __restrict__ sids, const int* __restrict__ eff_lens,
        const float* __restrict__ noise, float* __restrict__ out,
        const float* __restrict__ fs,
        const float* __restrict__ w1, const float* __restrict__ b1,
        const float* __restrict__ w2, const float* __restrict__ b2,
        const float* __restrict__ W) {
    __shared__ unsigned long long s_keys[LL];   // 32 KB (prep) / reused by fs
    __shared__ int s_hist[NB + 1];
    __shared__ int s_wsum[32];
    __shared__ int s_ns;

    int t = threadIdx.x;
    int lane = t & 31, wid = t >> 5;

    // ======================= role: convW (blocks 32..47) ====================
    if (blockIdx.x >= 32) {
        int gid = (blockIdx.x - 32) * 1024 + t;   // 16384 items
        int row = gid >> 6;          // 0..255
        int g   = gid & 63;          // col group of 8 f32 (k = g*8..g*8+7)
        int c   = g >> 2;            // k32 chunk = (g*8)/32
        int kk  = (g & 3) * 8;       // k within chunk
        float4 v0 = *(const float4*)&W[(size_t)row * PD + g * 8];
        float4 v1 = *(const float4*)&W[(size_t)row * PD + g * 8 + 4];
        float a[8] = {v0.x, v0.y, v0.z, v0.w, v1.x, v1.y, v1.z, v1.w};
        uint32_t o[8];
#pragma unroll
        for (int i = 0; i < 8; i++) o[i] = f2tf32(a[i]);
        uint32_t* dst = &g_Bs[c * 8192 + row * 32 + kk];
        *(uint4*)(dst)     = make_uint4(o[0], o[1], o[2], o[3]);
        *(uint4*)(dst + 4) = make_uint4(o[4], o[5], o[6], o[7]);
        return;
    }

    // ======================= role: fs MLP (blocks 16..31) ===================
    if (blockIdx.x >= 16) {
        int b = blockIdx.x - 16;
        float* tf = (float*)s_keys;        // 256 floats
        float* h1 = tf + 256;              // 256 floats
        if (t < 128) {
            float fr = expf(-9.2103403719761836f * (float)t * (1.0f / 128.0f));
            float arg = fs[b] * fr;
            tf[t] = cosf(arg);
            tf[t + 128] = sinf(arg);
        }
        __syncthreads();
        {   // layer 1: 32 warps x 8 outputs each
            float tv[8];
#pragma unroll
            for (int i = 0; i < 8; i++) tv[i] = tf[lane * 8 + i];
#pragma unroll
            for (int j = 0; j < 8; j++) {
                int h = wid * 8 + j;
                float4 a0 = *(const float4*)&w1[h * 256 + lane * 8];
                float4 a1 = *(const float4*)&w1[h * 256 + lane * 8 + 4];
                float s = tv[0]*a0.x + tv[1]*a0.y + tv[2]*a0.z + tv[3]*a0.w
                        + tv[4]*a1.x + tv[5]*a1.y + tv[6]*a1.z + tv[7]*a1.w;
#pragma unroll
                for (int d = 16; d > 0; d >>= 1) s += __shfl_down_sync(0xffffffffu, s, d);
                if (lane == 0) { s += b1[h]; h1[h] = s / (1.0f + expf(-s)); }
            }
        }
        __syncthreads();
        {   // layer 2
            float hv[8];
#pragma unroll
            for (int i = 0; i < 8; i++) hv[i] = h1[lane * 8 + i];
#pragma unroll
            for (int j = 0; j < 8; j++) {
                int h = wid * 8 + j;
                float4 a0 = *(const float4*)&w2[h * 256 + lane * 8];
                float4 a1 = *(const float4*)&w2[h * 256 + lane * 8 + 4];
                float s = hv[0]*a0.x + hv[1]*a0.y + hv[2]*a0.z + hv[3]*a0.w
                        + hv[4]*a1.x + hv[5]*a1.y + hv[6]*a1.z + hv[7]*a1.w;
#pragma unroll
                for (int d = 16; d > 0; d >>= 1) s += __shfl_down_sync(0xffffffffu, s, d);
                if (lane == 0) g_fsemb[b * 256 + h] = s + b2[h];
            }
        }
        return;
    }

    // ======================= role: prep (blocks 0..15) ======================
    int b = blockIdx.x;
    int eff = eff_lens[b];
    int base = t * 4;

    s_hist[t] = 0;
    if (t < NB + 1 - 1024) s_hist[1024 + t] = 0;
    if (t == 0) { s_hist[NB] = 0; s_ns = 0; }

    int4  sd4 = *(const int4*)  &sids [b * LL + base];
    float4 nz4 = *(const float4*)&noise[b * LL + base];
    int sm1 = (base >= 1) ? sids[b * LL + base - 1] : -1;
    int sm2 = (base >= 2) ? sids[b * LL + base - 2] : -1;
    __syncthreads();

    int   sd[6] = {sm2, sm1, sd4.x, sd4.y, sd4.z, sd4.w};
    float nz[4] = {nz4.x, nz4.y, nz4.z, nz4.w};

    unsigned long long key[4];
    int bid[4], slot[4];
    int nseg = 0;
#pragma unroll
    for (int i = 0; i < 4; i++) {
        int l = base + i;
        bool valid = l < eff;
        bool seg = valid && (sd[i + 2] != sd[i + 1]);
        bool fst = valid && (l >= 1) && (sd[i + 1] != sd[i]);
        nseg += seg ? 1 : 0;
        float v = (seg || fst) ? 0.0f : nz[i];
        unsigned int bits = __float_as_uint(v);
        key[i] = ((unsigned long long)bits << 12) | (unsigned)l;
        bid[i] = min(NB - 1, (int)(v * (float)NB));
        if (valid) slot[i] = atomicAdd(&s_hist[bid[i]], 1);
    }
    {
        int v = nseg;
#pragma unroll
        for (int d = 16; d > 0; d >>= 1) v += __shfl_down_sync(0xffffffffu, v, d);
        if (lane == 0 && v) atomicAdd(&s_ns, v);
    }
    __syncthreads();

    int ns = s_ns;
    int lk = 2 * ns + (int)((float)(eff - 2 * ns) * 0.25f);

    int c0 = s_hist[2 * t], c1 = s_hist[2 * t + 1];
    int ex = block_exscan(c0 + c1, s_wsum);
    s_hist[2 * t] = ex;
    s_hist[2 * t + 1] = ex + c0;
    if (t == 1023) s_hist[NB] = ex + c0 + c1;
    __syncthreads();

#pragma unroll
    for (int i = 0; i < 4; i++) {
        int l = base + i;
        if (l < eff) s_keys[s_hist[bid[i]] + slot[i]] = key[i];
    }
    __syncthreads();

    int r[4];
    bool kept[4];
    int cnt = 0;
#pragma unroll
    for (int i = 0; i < 4; i++) {
        int l = base + i;
        if (l < eff) {
            int lo = s_hist[bid[i]], hi = s_hist[bid[i] + 1];
            int c = 0;
            for (int m = lo; m < hi; m++) c += (s_keys[m] < key[i]) ? 1 : 0;
            r[i] = lo + c;
        } else {
            r[i] = l;
        }
        kept[i] = (l < eff) && (r[i] < lk);
        cnt += kept[i] ? 1 : 0;
    }
    __syncthreads();

    int p = block_exscan(cnt, s_wsum);

    const size_t O1 = (size_t)BB * LL * HH;
    const size_t O2 = O1 + (size_t)BB * LL;
    const size_t O3 = O2 + (size_t)BB * LL;
    float* mae = out + O1 + (size_t)b * LL;
    float* rst = out + O2 + (size_t)b * LL;
    float* unm = out + O3 + (size_t)b * LL;

#pragma unroll
    for (int i = 0; i < 4; i++) {
        int l = base + i;
        mae[l] = (l < eff && !kept[i]) ? 1.0f : 0.0f;
        rst[l] = (float)(kept[i] ? p : r[i]);
        if (kept[i]) {
            g_keptlist[b * LL + p] = l;
            unm[p] = (float)sd[i + 2];
            p++;
        }
        if (l >= lk) unm[l] = -1.0f;
    }
    if (t == 0) g_lenkeep[b] = lk;
}

// ---------------------------------------------------------------------------
// k_gemm: tf32 mma.sync GEMM, cvt-after-ldsm A path, 3-stage cp.async.
// Block (256 thr, 8 warps) = (M-tile 128, N-half 128, batch); 2 CTAs/SM.
// 16 K-chunks of 32.  A raw fp32 cp.async (gathered rows); converted to tf32
// in fragment registers after ldmatrix.  B tf32 from g_Bs.
// Pipeline: wait_group(1) -> sync -> issue copy(c+2) -> MMA(c).
// SMEM from 128-aligned base AB:
//   0: sBF[128]f  512: sKL[128]i
//   2048:  A bufs x3 (16 KB each) = 48 KB  (ends 51200)
//   51200: B bufs x3 (16 KB each) = 48 KB  (ends 100352)
// ---------------------------------------------------------------------------
#define SM_A 2048
#define SM_B 51200
#define SMEMSZ (100352 + 128)

__global__ void __launch_bounds__(256, 2)
k_gemm(const float* __restrict__ patches,
       const float* __restrict__ bias, const float* __restrict__ pos,
       float* __restrict__ out_seq) {
    extern __shared__ char dsm[];
    int b  = blockIdx.z;
    int n0 = blockIdx.y * 128;
    int p0 = blockIdx.x * 128;
    int lk = g_lenkeep[b];
    int t = threadIdx.x;

    // ---- pure-zero blocks: whole tile is tail (block-uniform branch) ----
    if (p0 >= lk) {
        float4 z = make_float4(0.f, 0.f, 0.f, 0.f);
#pragma unroll
        for (int i = 0; i < 16; i++) {
            int idx = t + i * 256;       // 4096 float4s: 128 rows x 32 f4
            int row = idx >> 5, c4 = idx & 31;
            *((float4*)&out_seq[((size_t)b * LL + p0 + row) * HH + n0] + c4) = z;
        }
        return;
    }

    uint32_t AB = (smem_u32(dsm) + 127u) & ~127u;
    char* ABp = dsm + (AB - smem_u32(dsm));
    float* sBF = (float*)(ABp);
    int*   sKL = (int*)(ABp + 512);

    int lane = t & 31, wid = t >> 5;
    int wm = wid & 3, wn = wid >> 2;     // 4 M-groups(32) x 2 N-groups(64)

    if (t < 128) {
        sBF[t] = bias[n0 + t] + g_fsemb[b * HH + n0 + t];
        int p = p0 + t;
        sKL[t] = (p < lk) ? g_keptlist[b * LL + p] : 0;
    }
    __syncthreads();   // sKL needed for copy addresses

    // ---- A copy: 1024 segs (128 rows x 8 segs of 16B) -> 4 per thread ----
    const float* aSrc[4];
    uint32_t aDst[4];
#pragma unroll
    for (int i = 0; i < 4; i++) {
        int sid = t + i * 256;
        int r = sid >> 3, s = sid & 7;
        aSrc[i] = &patches[((size_t)b * LL + sKL[r]) * PD + s * 4];
        aDst[i] = AB + SM_A + (uint32_t)(r * 128 + ((s ^ (r & 7)) * 16));
    }
    // ---- B copy: 1024 segs (128 n rows x 8 segs) -> 4 per thread ----
    uint32_t bDst[4];
    int bSrcOff[4];
#pragma unroll
    for (int i = 0; i < 4; i++) {
        int sid = t + i * 256;
        int r = sid >> 3, s = sid & 7;
        bDst[i] = AB + SM_B + (uint32_t)(r * 128 + ((s ^ (r & 7)) * 16));
        bSrcOff[i] = (n0 + r) * 32 + s * 4;
    }

    // ---- ldmatrix address components ----
    uint32_t aRB[2], aXP[2];
#pragma unroll
    for (int mt = 0; mt < 2; mt++) {
        int rowA = wm * 32 + mt * 16 + (((lane >> 3) & 1) * 8) + (lane & 7);
        aRB[mt] = AB + SM_A + (uint32_t)(rowA * 128);
        aXP[mt] = (uint32_t)((rowA & 7) << 4);
    }
    uint32_t aSG = (uint32_t)((lane >> 4) * 16);
    uint32_t bRB[4], bXP[4];
#pragma unroll
    for (int g = 0; g < 4; g++) {
        int rowB = wn * 64 + g * 16 + ((lane >> 4) << 3) + (lane & 7);  // 0..127
        bRB[g] = AB + SM_B + (uint32_t)(rowB * 128);
        bXP[g] = (uint32_t)((rowB & 7) << 4);
    }
    uint32_t bSG = (uint32_t)(((lane >> 3) & 1) * 16);

    float acc[2][8][4];
#pragma unroll
    for (int mt = 0; mt < 2; mt++)
#pragma unroll
        for (int nt = 0; nt < 8; nt++)
#pragma unroll
            for (int i = 0; i < 4; i++) acc[mt][nt][i] = 0.f;

    auto copy_chunk = [&](int c) {
        uint32_t off = (uint32_t)(c % 3) * 16384u;
        const uint32_t* Bg = &g_Bs[c * 8192];
#pragma unroll
        for (int i = 0; i < 4; i++) cp16(aDst[i] + off, aSrc[i] + c * 32);
#pragma unroll
        for (int i = 0; i < 4; i++) cp16(bDst[i] + off, Bg + bSrcOff[i]);
        CP_COMMIT();
    };

    copy_chunk(0);
    copy_chunk(1);

    for (int c = 0; c < NCH; c++) {
        if (c + 1 < NCH) asm volatile("cp.async.wait_group 1;" ::: "memory");
        else             asm volatile("cp.async.wait_group 0;" ::: "memory");
        __syncthreads();
        if (c + 2 < NCH) copy_chunk(c + 2);   // into buf freed by MMA(c-1)

        uint32_t off = (uint32_t)(c % 3) * 16384u;
        // ---- MMA: 4 k8-steps; A frags cvt'd to tf32 after ldsm ----
#pragma unroll
        for (int ks = 0; ks < 4; ks++) {
            uint32_t af[2][4], bf[4][4];
            uint32_t so = (uint32_t)(ks * 32);
#pragma unroll
            for (int mt = 0; mt < 2; mt++) {
                ldsm4(af[mt], aRB[mt] + off + ((so + aSG) ^ aXP[mt]));
#pragma unroll
                for (int i = 0; i < 4; i++)
                    af[mt][i] = f2tf32(__uint_as_float(af[mt][i]));
            }
#pragma unroll
            for (int g = 0; g < 4; g++)
                ldsm4(bf[g], bRB[g] + off + ((so + bSG) ^ bXP[g]));
#pragma unroll
            for (int mt = 0; mt < 2; mt++)
#pragma unroll
                for (int nt = 0; nt < 8; nt++)
                    mma_tf32(acc[mt][nt], af[mt],
                             bf[nt >> 1][(nt & 1) * 2], bf[nt >> 1][(nt & 1) * 2 + 1]);
        }
    }

    // ---- epilogue: acc + bias + fsemb + pos -> out; tail rows -> 0 ----
#pragma unroll
    for (int mt = 0; mt < 2; mt++) {
        int rbase = wm * 32 + mt * 16 + (lane >> 2);
#pragma unroll
        for (int h = 0; h < 2; h++) {
            int rr = rbase + h * 8;
            int p = p0 + rr;
            int kl = sKL[rr];
            bool ok = p < lk;
            float* orow = &out_seq[(((size_t)b * LL) + p) * HH + n0];
            const float* prow = &pos[(size_t)kl * HH + n0];
#pragma unroll
            for (int nt = 0; nt < 8; nt++) {
                int col = wn * 64 + nt * 8 + (lane & 3) * 2;
                float2 v;
                if (ok) {
                    v.x = acc[mt][nt][h * 2 + 0] + sBF[col]     + prow[col];
                    v.y = acc[mt][nt][h * 2 + 1] + sBF[col + 1] + prow[col + 1];
                } else {
                    v.x = 0.f; v.y = 0.f;
                }
                *(float2*)&orow[col] = v;
            }
        }
    }
}

// ---------------------------------------------------------------------------
extern "C" void kernel_launch(void* const* d_in, const int* in_sizes, int n_in,
                              void* d_out, int out_size) {
    const float* patches = (const float*)d_in[0];
    const int*   sids    = (const int*)  d_in[1];
    const int*   eff     = (const int*)  d_in[2];
    const float* noise   = (const float*)d_in[3];
    const float* fs      = (const float*)d_in[4];
    const float* W       = (const float*)d_in[5];
    const float* bias    = (const float*)d_in[6];
    const float* pos     = (const float*)d_in[7];
    const float* w1      = (const float*)d_in[8];
    const float* b1      = (const float*)d_in[9];
    const float* w2      = (const float*)d_in[10];
    const float* b2      = (const float*)d_in[11];
    float* out = (float*)d_out;

    cudaFuncSetAttribute(k_gemm, cudaFuncAttributeMaxDynamicSharedMemorySize, SMEMSZ);

    k_front<<<48, 1024>>>(sids, eff, noise, out, fs, w1, b1, w2, b2, W);
    k_gemm<<<dim3(32, 2, BB), 256, SMEMSZ>>>(patches, bias, pos, out);

    (void)in_sizes; (void)n_in; (void)out_size;
}

// round 16
// speedup vs baseline: 1.4518x; 1.0387x over previous
#include <cuda_runtime.h>
#include <cuda_bf16.h>
#include <math.h>
#include <stdint.h>

#define BB 16
#define LL 4096
#define PD 512
#define HH 256
#define NB 2048            // rank buckets
#define NCH 16             // K chunks of 32 fp32 cols
#define NWORK 296          // persistent gemm workers (2/SM x 148)

// ---------------------------------------------------------------------------
// scratch (static device memory — no allocations allowed)
// ---------------------------------------------------------------------------
__device__ int   g_keptlist[BB * LL];
__device__ int   g_lenkeep[BB];
__device__ float g_fsemb[BB * HH];
// W as tf32 (u32): 16 chunks x [256 rows x 32 k] = 8192 u32 each; 512 KB
__device__ __align__(1024) uint32_t g_Bs[16 * 8192];

// ---------------------------------------------------------------------------
// PTX helpers (plain sm_80/90 PTX — no 'a'-gated instructions)
// ---------------------------------------------------------------------------
__device__ __forceinline__ uint32_t smem_u32(const void* p) {
    uint32_t a;
    asm("{ .reg .u64 t; cvta.to.shared.u64 t, %1; cvt.u32.u64 %0, t; }" : "=r"(a) : "l"(p));
    return a;
}
__device__ __forceinline__ void cp16(uint32_t s, const void* g) {
    asm volatile("cp.async.cg.shared.global [%0], [%1], 16;" :: "r"(s), "l"(g));
}
#define CP_COMMIT() asm volatile("cp.async.commit_group;" ::: "memory")

__device__ __forceinline__ void ldsm4(uint32_t* r, uint32_t a) {
    asm volatile("ldmatrix.sync.aligned.m8n8.x4.shared.b16 {%0,%1,%2,%3}, [%4];"
                 : "=r"(r[0]), "=r"(r[1]), "=r"(r[2]), "=r"(r[3]) : "r"(a));
}
__device__ __forceinline__ uint32_t f2tf32(float x) {
    uint32_t u;
    asm("cvt.rna.tf32.f32 %0, %1;" : "=r"(u) : "f"(x));
    return u;
}
__device__ __forceinline__ void mma_tf32(float* d, const uint32_t* a,
                                         uint32_t b0, uint32_t b1) {
    asm volatile(
        "mma.sync.aligned.m16n8k8.row.col.f32.tf32.tf32.f32 "
        "{%0,%1,%2,%3}, {%4,%5,%6,%7}, {%8,%9}, {%0,%1,%2,%3};"
        : "+f"(d[0]), "+f"(d[1]), "+f"(d[2]), "+f"(d[3])
        : "r"(a[0]), "r"(a[1]), "r"(a[2]), "r"(a[3]), "r"(b0), "r"(b1));
}

// ---------------------------------------------------------------------------
// block-wide exclusive scan over one int per thread (1024 threads)
// ---------------------------------------------------------------------------
__device__ __forceinline__ int block_exscan(int v, int* wsum) {
    int lane = threadIdx.x & 31, wid = threadIdx.x >> 5;
    int inc = v;
#pragma unroll
    for (int d = 1; d < 32; d <<= 1) {
        int u = __shfl_up_sync(0xffffffffu, inc, d);
        if (lane >= d) inc += u;
    }
    if (lane == 31) wsum[wid] = inc;
    __syncthreads();
    if (wid == 0) {
        int s = wsum[lane];
#pragma unroll
        for (int d = 1; d < 32; d <<= 1) {
            int u = __shfl_up_sync(0xffffffffu, s, d);
            if (lane >= d) s += u;
        }
        wsum[lane] = s;
    }
    __syncthreads();
    return ((wid > 0) ? wsum[wid - 1] : 0) + (inc - v);
}

// ---------------------------------------------------------------------------
// k_front: role-dispatched front kernel, grid 48 x 1024 threads.
//   blocks  0..15 : prep (sort/rank/scan) for batch b = blockIdx.x
//   blocks 16..31 : timestep MLP (both layers) for b = blockIdx.x - 16
//   blocks 32..47 : W fp32 -> tf32 conversion (1/16 slice each)
// ---------------------------------------------------------------------------
__global__ void __launch_bounds__(1024, 1)
k_front(const int* __restrict__ sids, const int* __restrict__ eff_lens,
        const float* __restrict__ noise, float* __restrict__ out,
        const float* __restrict__ fs,
        const float* __restrict__ w1, const float* __restrict__ b1,
        const float* __restrict__ w2, const float* __restrict__ b2,
        const float* __restrict__ W) {
    __shared__ unsigned long long s_keys[LL];   // 32 KB (prep) / reused by fs
    __shared__ int s_hist[NB + 1];
    __shared__ int s_wsum[32];
    __shared__ int s_ns;

    int t = threadIdx.x;
    int lane = t & 31, wid = t >> 5;

    // ======================= role: convW (blocks 32..47) ====================
    if (blockIdx.x >= 32) {
        int gid = (blockIdx.x - 32) * 1024 + t;   // 16384 items
        int row = gid >> 6;          // 0..255
        int g   = gid & 63;          // col group of 8 f32 (k = g*8..g*8+7)
        int c   = g >> 2;            // k32 chunk = (g*8)/32
        int kk  = (g & 3) * 8;       // k within chunk
        float4 v0 = *(const float4*)&W[(size_t)row * PD + g * 8];
        float4 v1 = *(const float4*)&W[(size_t)row * PD + g * 8 + 4];
        float a[8] = {v0.x, v0.y, v0.z, v0.w, v1.x, v1.y, v1.z, v1.w};
        uint32_t o[8];
#pragma unroll
        for (int i = 0; i < 8; i++) o[i] = f2tf32(a[i]);
        uint32_t* dst = &g_Bs[c * 8192 + row * 32 + kk];
        *(uint4*)(dst)     = make_uint4(o[0], o[1], o[2], o[3]);
        *(uint4*)(dst + 4) = make_uint4(o[4], o[5], o[6], o[7]);
        return;
    }

    // ======================= role: fs MLP (blocks 16..31) ===================
    if (blockIdx.x >= 16) {
        int b = blockIdx.x - 16;
        float* tf = (float*)s_keys;        // 256 floats
        float* h1 = tf + 256;              // 256 floats
        if (t < 128) {
            float fr = expf(-9.2103403719761836f * (float)t * (1.0f / 128.0f));
            float arg = fs[b] * fr;
            tf[t] = cosf(arg);
            tf[t + 128] = sinf(arg);
        }
        __syncthreads();
        {   // layer 1: 32 warps x 8 outputs each
            float tv[8];
#pragma unroll
            for (int i = 0; i < 8; i++) tv[i] = tf[lane * 8 + i];
#pragma unroll
            for (int j = 0; j < 8; j++) {
                int h = wid * 8 + j;
                float4 a0 = *(const float4*)&w1[h * 256 + lane * 8];
                float4 a1 = *(const float4*)&w1[h * 256 + lane * 8 + 4];
                float s = tv[0]*a0.x + tv[1]*a0.y + tv[2]*a0.z + tv[3]*a0.w
                        + tv[4]*a1.x + tv[5]*a1.y + tv[6]*a1.z + tv[7]*a1.w;
#pragma unroll
                for (int d = 16; d > 0; d >>= 1) s += __shfl_down_sync(0xffffffffu, s, d);
                if (lane == 0) { s += b1[h]; h1[h] = s / (1.0f + expf(-s)); }
            }
        }
        __syncthreads();
        {   // layer 2
            float hv[8];
#pragma unroll
            for (int i = 0; i < 8; i++) hv[i] = h1[lane * 8 + i];
#pragma unroll
            for (int j = 0; j < 8; j++) {
                int h = wid * 8 + j;
                float4 a0 = *(const float4*)&w2[h * 256 + lane * 8];
                float4 a1 = *(const float4*)&w2[h * 256 + lane * 8 + 4];
                float s = hv[0]*a0.x + hv[1]*a0.y + hv[2]*a0.z + hv[3]*a0.w
                        + hv[4]*a1.x + hv[5]*a1.y + hv[6]*a1.z + hv[7]*a1.w;
#pragma unroll
                for (int d = 16; d > 0; d >>= 1) s += __shfl_down_sync(0xffffffffu, s, d);
                if (lane == 0) g_fsemb[b * 256 + h] = s + b2[h];
            }
        }
        return;
    }

    // ======================= role: prep (blocks 0..15) ======================
    int b = blockIdx.x;
    int eff = eff_lens[b];
    int base = t * 4;

    s_hist[t] = 0;
    if (t < NB + 1 - 1024) s_hist[1024 + t] = 0;
    if (t == 0) { s_hist[NB] = 0; s_ns = 0; }

    int4  sd4 = *(const int4*)  &sids [b * LL + base];
    float4 nz4 = *(const float4*)&noise[b * LL + base];
    int sm1 = (base >= 1) ? sids[b * LL + base - 1] : -1;
    int sm2 = (base >= 2) ? sids[b * LL + base - 2] : -1;
    __syncthreads();

    int   sd[6] = {sm2, sm1, sd4.x, sd4.y, sd4.z, sd4.w};
    float nz[4] = {nz4.x, nz4.y, nz4.z, nz4.w};

    unsigned long long key[4];
    int bid[4], slot[4];
    int nseg = 0;
#pragma unroll
    for (int i = 0; i < 4; i++) {
        int l = base + i;
        bool valid = l < eff;
        bool seg = valid && (sd[i + 2] != sd[i + 1]);
        bool fst = valid && (l >= 1) && (sd[i + 1] != sd[i]);
        nseg += seg ? 1 : 0;
        float v = (seg || fst) ? 0.0f : nz[i];
        unsigned int bits = __float_as_uint(v);
        key[i] = ((unsigned long long)bits << 12) | (unsigned)l;
        bid[i] = min(NB - 1, (int)(v * (float)NB));
        if (valid) slot[i] = atomicAdd(&s_hist[bid[i]], 1);
    }
    {
        int v = nseg;
#pragma unroll
        for (int d = 16; d > 0; d >>= 1) v += __shfl_down_sync(0xffffffffu, v, d);
        if (lane == 0 && v) atomicAdd(&s_ns, v);
    }
    __syncthreads();

    int ns = s_ns;
    int lk = 2 * ns + (int)((float)(eff - 2 * ns) * 0.25f);

    int c0 = s_hist[2 * t], c1 = s_hist[2 * t + 1];
    int ex = block_exscan(c0 + c1, s_wsum);
    s_hist[2 * t] = ex;
    s_hist[2 * t + 1] = ex + c0;
    if (t == 1023) s_hist[NB] = ex + c0 + c1;
    __syncthreads();

#pragma unroll
    for (int i = 0; i < 4; i++) {
        int l = base + i;
        if (l < eff) s_keys[s_hist[bid[i]] + slot[i]] = key[i];
    }
    __syncthreads();

    int r[4];
    bool kept[4];
    int cnt = 0;
#pragma unroll
    for (int i = 0; i < 4; i++) {
        int l = base + i;
        if (l < eff) {
            int lo = s_hist[bid[i]], hi = s_hist[bid[i] + 1];
            int c = 0;
            for (int m = lo; m < hi; m++) c += (s_keys[m] < key[i]) ? 1 : 0;
            r[i] = lo + c;
        } else {
            r[i] = l;
        }
        kept[i] = (l < eff) && (r[i] < lk);
        cnt += kept[i] ? 1 : 0;
    }
    __syncthreads();

    int p = block_exscan(cnt, s_wsum);

    const size_t O1 = (size_t)BB * LL * HH;
    const size_t O2 = O1 + (size_t)BB * LL;
    const size_t O3 = O2 + (size_t)BB * LL;
    float* mae = out + O1 + (size_t)b * LL;
    float* rst = out + O2 + (size_t)b * LL;
    float* unm = out + O3 + (size_t)b * LL;

#pragma unroll
    for (int i = 0; i < 4; i++) {
        int l = base + i;
        mae[l] = (l < eff && !kept[i]) ? 1.0f : 0.0f;
        rst[l] = (float)(kept[i] ? p : r[i]);
        if (kept[i]) {
            g_keptlist[b * LL + p] = l;
            unm[p] = (float)sd[i + 2];
            p++;
        }
        if (l >= lk) unm[l] = -1.0f;
    }
    if (t == 0) g_lenkeep[b] = lk;
}

// ---------------------------------------------------------------------------
// k_gemm: persistent balanced tf32 GEMM.  Grid = NWORK blocks of 256 threads
// (2 CTAs/SM); each worker strides the 1024 virtual tiles v = m*32 + h*16 + b
// (m-major), so real tiles (m*128 < lk) land in the low-v region: <= 1 real
// tile per worker; remaining strides are cheap zero-fills.
// Per real tile: 16 K-chunks of 32, A raw fp32 cp.async (gathered rows),
// cvt to tf32 in fragment regs after ldmatrix; B tf32 from g_Bs; 3-stage
// cp.async pipeline (wait(1) -> sync -> copy(c+2) -> MMA(c)).
// SMEM from 128-aligned base AB:
//   0: sBF[128]f  512: sKL[128]i
//   2048:  A bufs x3 (16 KB) = 48 KB (ends 51200)
//   51200: B bufs x3 (16 KB) = 48 KB (ends 100352)
// ---------------------------------------------------------------------------
#define SM_A 2048
#define SM_B 51200
#define SMEMSZ (100352 + 128)

__global__ void __launch_bounds__(256, 2)
k_gemm(const float* __restrict__ patches,
       const float* __restrict__ bias, const float* __restrict__ pos,
       float* __restrict__ out_seq) {
    extern __shared__ char dsm[];
    int t = threadIdx.x;
    int lane = t & 31, wid = t >> 5;
    int wm = wid & 3, wn = wid >> 2;     // 4 M-groups(32) x 2 N-groups(64)

    uint32_t AB = (smem_u32(dsm) + 127u) & ~127u;
    char* ABp = dsm + (AB - smem_u32(dsm));
    float* sBF = (float*)(ABp);
    int*   sKL = (int*)(ABp + 512);

    for (int v = blockIdx.x; v < 32 * 2 * BB; v += NWORK) {
        int b  = v & 15;
        int n0 = ((v >> 4) & 1) * 128;
        int p0 = (v >> 5) * 128;
        int lk = g_lenkeep[b];

        // ---- zero tile ----
        if (p0 >= lk) {
            float4 z = make_float4(0.f, 0.f, 0.f, 0.f);
#pragma unroll
            for (int i = 0; i < 16; i++) {
                int idx = t + i * 256;       // 4096 float4s: 128 rows x 32 f4
                int row = idx >> 5, c4 = idx & 31;
                *((float4*)&out_seq[((size_t)b * LL + p0 + row) * HH + n0] + c4) = z;
            }
            continue;
        }

        // ---- real tile ----
        __syncthreads();   // protect smem from prior iteration's readers
        if (t < 128) {
            sBF[t] = bias[n0 + t] + g_fsemb[b * HH + n0 + t];
            int p = p0 + t;
            sKL[t] = (p < lk) ? g_keptlist[b * LL + p] : 0;
        }
        __syncthreads();   // sKL needed for copy addresses

        // ---- A copy: 1024 segs (128 rows x 8 segs of 16B) -> 4/thread ----
        const float* aSrc[4];
        uint32_t aDst[4];
#pragma unroll
        for (int i = 0; i < 4; i++) {
            int sid = t + i * 256;
            int r = sid >> 3, s = sid & 7;
            aSrc[i] = &patches[((size_t)b * LL + sKL[r]) * PD + s * 4];
            aDst[i] = AB + SM_A + (uint32_t)(r * 128 + ((s ^ (r & 7)) * 16));
        }
        // ---- B copy: 1024 segs -> 4/thread ----
        uint32_t bDst[4];
        int bSrcOff[4];
#pragma unroll
        for (int i = 0; i < 4; i++) {
            int sid = t + i * 256;
            int r = sid >> 3, s = sid & 7;
            bDst[i] = AB + SM_B + (uint32_t)(r * 128 + ((s ^ (r & 7)) * 16));
            bSrcOff[i] = (n0 + r) * 32 + s * 4;
        }

        // ---- ldmatrix address components ----
        uint32_t aRB[2], aXP[2];
#pragma unroll
        for (int mt = 0; mt < 2; mt++) {
            int rowA = wm * 32 + mt * 16 + (((lane >> 3) & 1) * 8) + (lane & 7);
            aRB[mt] = AB + SM_A + (uint32_t)(rowA * 128);
            aXP[mt] = (uint32_t)((rowA & 7) << 4);
        }
        uint32_t aSG = (uint32_t)((lane >> 4) * 16);
        uint32_t bRB[4], bXP[4];
#pragma unroll
        for (int g = 0; g < 4; g++) {
            int rowB = wn * 64 + g * 16 + ((lane >> 4) << 3) + (lane & 7);
            bRB[g] = AB + SM_B + (uint32_t)(rowB * 128);
            bXP[g] = (uint32_t)((rowB & 7) << 4);
        }
        uint32_t bSG = (uint32_t)(((lane >> 3) & 1) * 16);

        float acc[2][8][4];
#pragma unroll
        for (int mt = 0; mt < 2; mt++)
#pragma unroll
            for (int nt = 0; nt < 8; nt++)
#pragma unroll
                for (int i = 0; i < 4; i++) acc[mt][nt][i] = 0.f;

        auto copy_chunk = [&](int c) {
            uint32_t off = (uint32_t)(c % 3) * 16384u;
            const uint32_t* Bg = &g_Bs[c * 8192];
#pragma unroll
            for (int i = 0; i < 4; i++) cp16(aDst[i] + off, aSrc[i] + c * 32);
#pragma unroll
            for (int i = 0; i < 4; i++) cp16(bDst[i] + off, Bg + bSrcOff[i]);
            CP_COMMIT();
        };

        copy_chunk(0);
        copy_chunk(1);

        for (int c = 0; c < NCH; c++) {
            if (c + 1 < NCH) asm volatile("cp.async.wait_group 1;" ::: "memory");
            else             asm volatile("cp.async.wait_group 0;" ::: "memory");
            __syncthreads();
            if (c + 2 < NCH) copy_chunk(c + 2);   // into buf freed by MMA(c-1)

            uint32_t off = (uint32_t)(c % 3) * 16384u;
#pragma unroll
            for (int ks = 0; ks < 4; ks++) {
                uint32_t af[2][4], bf[4][4];
                uint32_t so = (uint32_t)(ks * 32);
#pragma unroll
                for (int mt = 0; mt < 2; mt++) {
                    ldsm4(af[mt], aRB[mt] + off + ((so + aSG) ^ aXP[mt]));
#pragma unroll
                    for (int i = 0; i < 4; i++)
                        af[mt][i] = f2tf32(__uint_as_float(af[mt][i]));
                }
#pragma unroll
                for (int g = 0; g < 4; g++)
                    ldsm4(bf[g], bRB[g] + off + ((so + bSG) ^ bXP[g]));
#pragma unroll
                for (int mt = 0; mt < 2; mt++)
#pragma unroll
                    for (int nt = 0; nt < 8; nt++)
                        mma_tf32(acc[mt][nt], af[mt],
                                 bf[nt >> 1][(nt & 1) * 2], bf[nt >> 1][(nt & 1) * 2 + 1]);
            }
        }

        // ---- epilogue ----
#pragma unroll
        for (int mt = 0; mt < 2; mt++) {
            int rbase = wm * 32 + mt * 16 + (lane >> 2);
#pragma unroll
            for (int h2 = 0; h2 < 2; h2++) {
                int rr = rbase + h2 * 8;
                int p = p0 + rr;
                int kl = sKL[rr];
                bool ok = p < lk;
                float* orow = &out_seq[(((size_t)b * LL) + p) * HH + n0];
                const float* prow = &pos[(size_t)kl * HH + n0];
#pragma unroll
                for (int nt = 0; nt < 8; nt++) {
                    int col = wn * 64 + nt * 8 + (lane & 3) * 2;
                    float2 vv;
                    if (ok) {
                        vv.x = acc[mt][nt][h2 * 2 + 0] + sBF[col]     + prow[col];
                        vv.y = acc[mt][nt][h2 * 2 + 1] + sBF[col + 1] + prow[col + 1];
                    } else {
                        vv.x = 0.f; vv.y = 0.f;
                    }
                    *(float2*)&orow[col] = vv;
                }
            }
        }
    }
}

// ---------------------------------------------------------------------------
extern "C" void kernel_launch(void* const* d_in, const int* in_sizes, int n_in,
                              void* d_out, int out_size) {
    const float* patches = (const float*)d_in[0];
    const int*   sids    = (const int*)  d_in[1];
    const int*   eff     = (const int*)  d_in[2];
    const float* noise   = (const float*)d_in[3];
    const float* fs      = (const float*)d_in[4];
    const float* W       = (const float*)d_in[5];
    const float* bias    = (const float*)d_in[6];
    const float* pos     = (const float*)d_in[7];
    const float* w1      = (const float*)d_in[8];
    const float* b1      = (const float*)d_in[9];
    const float* w2      = (const float*)d_in[10];
    const float* b2      = (const float*)d_in[11];
    float* out = (float*)d_out;

    cudaFuncSetAttribute(k_gemm, cudaFuncAttributeMaxDynamicSharedMemorySize, SMEMSZ);

    k_front<<<48, 1024>>>(sids, eff, noise, out, fs, w1, b1, w2, b2, W);
    k_gemm<<<NWORK, 256, SMEMSZ>>>(patches, bias, pos, out);

    (void)in_sizes; (void)n_in; (void)out_size;
}